// round 1
// baseline (speedup 1.0000x reference)
#include <cuda_runtime.h>
#include <math.h>

typedef unsigned long long ull;

#define EPS 1e-5f

// ---------------- scratch (device globals; no allocations allowed) ----------
__device__ float  g_om[8 * 27 * 64 * 64];          // offset-conv output
__device__ float  g_out1[8 * 256 * 64 * 64];       // DCN output (pre-BN)
__device__ float  g_raw[4 * 8 * 256 * 64 * 64];    // convT output per parity (pre-BN)
__device__ float  g_wdT2[9 * 256 * 512];           // DCN weights, [tap][c][o] duplicated pairs
__device__ float  g_woT[9 * 256 * 32];             // offset-conv weights [tap][c][o(pad32)]
__device__ float  g_wctT2[16 * 256 * 512];         // convT weights [par*4+tap][c][o] dup pairs
__device__ double g_red[1024];                     // sums/sumsqs for the two BNs
__device__ float  g_s1[256], g_t1[256], g_s2[256], g_t2[256];

// ---------------- packed f32x2 helpers --------------------------------------
__device__ __forceinline__ ull pk2(float a, float b) {
    ull r; asm("mov.b64 %0, {%1,%2};" : "=l"(r) : "f"(a), "f"(b)); return r;
}
__device__ __forceinline__ void upk2(ull v, float& a, float& b) {
    asm("mov.b64 {%0,%1}, %2;" : "=f"(a), "=f"(b) : "l"(v));
}
__device__ __forceinline__ void ffma2(ull& d, ull a, ull b) {
    asm("fma.rn.f32x2 %0, %1, %2, %0;" : "+l"(d) : "l"(a), "l"(b));
}

// ---------------- weight prep -----------------------------------------------
__global__ void prep_wd(const float* __restrict__ w) {  // w_dcn [o][c][3][3]
    int idx = blockIdx.x * blockDim.x + threadIdx.x;
    if (idx >= 9 * 256 * 256) return;
    int tap = idx >> 16, c = (idx >> 8) & 255, o = idx & 255;
    float v = w[((o << 8) + c) * 9 + tap];
    g_wdT2[(size_t)idx * 2] = v;
    g_wdT2[(size_t)idx * 2 + 1] = v;
}

__global__ void prep_wo(const float* __restrict__ w) {  // w_off [27][c][3][3]
    int idx = blockIdx.x * blockDim.x + threadIdx.x;
    if (idx >= 9 * 256 * 32) return;
    int tap = idx >> 13, c = (idx >> 5) & 255, o = idx & 31;
    g_woT[idx] = (o < 27) ? w[((o << 8) + c) * 9 + tap] : 0.f;
}

__global__ void prep_wct(const float* __restrict__ w) {  // w_ct [i][o][4][4]
    int idx = blockIdx.x * blockDim.x + threadIdx.x;
    if (idx >= 16 * 65536) return;
    int q = idx >> 16, c = (idx >> 8) & 255, o = idx & 255;
    int par = q >> 2, tp = q & 3;
    int py = par >> 1, px = par & 1, ty = tp >> 1, tx = tp & 1;
    int a = py ? (ty ? 0 : 2) : (ty ? 1 : 3);
    int b = px ? (tx ? 0 : 2) : (tx ? 1 : 3);
    float v = w[(((c << 8) + o) << 4) + (a << 2) + b];
    g_wctT2[(size_t)idx * 2] = v;
    g_wctT2[(size_t)idx * 2 + 1] = v;
}

__global__ void k_zero() {
    int t = threadIdx.x;
    g_red[t] = 0.0; g_red[256 + t] = 0.0; g_red[512 + t] = 0.0; g_red[768 + t] = 0.0;
}

// ---------------- offset conv: 256->27(pad 32), 3x3 SAME --------------------
__global__ void __launch_bounds__(256, 2) k_off(const float* __restrict__ x,
                                                const float* __restrict__ boff) {
    extern __shared__ float vsm[];             // [256 c][64 p]
    const int t = threadIdx.x, y = blockIdx.x, n = blockIdx.y;
    const int o  = t & 31;
    const int p0 = (t >> 5) * 8;
    const int p  = t & 63;
    const int cg = t >> 6;

    ull acc[4];
    float bo = (o < 27) ? boff[o] : 0.f;
    ull bb = pk2(bo, bo);
    acc[0] = bb; acc[1] = bb; acc[2] = bb; acc[3] = bb;

    const float* xn = x + ((size_t)n << 20);

    for (int tap = 0; tap < 9; tap++) {
        const int ki = tap / 3, kj = tap - 3 * ki;
        const int yy = y + ki - 1;
        const int xx = p + kj - 1;
        const bool valid = (yy >= 0) && (yy < 64) && (xx >= 0) && (xx < 64);
        const float* src = xn + yy * 64 + xx;
        #pragma unroll 4
        for (int i = 0; i < 64; i++) {
            const int c = cg + (i << 2);
            vsm[(c << 6) + p] = valid ? src[(size_t)c << 12] : 0.f;
        }
        __syncthreads();
        const float* wb = g_woT + ((tap << 8) << 5);
        #pragma unroll 2
        for (int c = 0; c < 256; c++) {
            float w = wb[(c << 5) + o];
            ull wd = pk2(w, w);
            const ulonglong2* vp = (const ulonglong2*)(vsm + (c << 6) + p0);
            ulonglong2 va = vp[0], vb = vp[1];
            ffma2(acc[0], wd, va.x);
            ffma2(acc[1], wd, va.y);
            ffma2(acc[2], wd, vb.x);
            ffma2(acc[3], wd, vb.y);
        }
        __syncthreads();
    }

    if (o < 27) {
        float f0,f1,f2,f3,f4,f5,f6,f7;
        upk2(acc[0], f0, f1); upk2(acc[1], f2, f3);
        upk2(acc[2], f4, f5); upk2(acc[3], f6, f7);
        float* op = g_om + (((size_t)(n * 27 + o) * 64 + y) << 6) + p0;
        *(float4*)op       = make_float4(f0, f1, f2, f3);
        *(float4*)(op + 4) = make_float4(f4, f5, f6, f7);
    }
}

// ---------------- DCNv2: gather + 9-tap GEMM --------------------------------
__global__ void __launch_bounds__(256, 2) k_dcn(const float* __restrict__ x,
                                                const float* __restrict__ bdcn) {
    extern __shared__ float vsm[];             // [256 c][64 p]
    const int t = threadIdx.x, y = blockIdx.x, n = blockIdx.y;
    const int o0 = (t & 31) * 8;
    const int p0 = (t >> 5) * 8;
    const int p  = t & 63;
    const int cg = t >> 6;

    ull acc[32];
    #pragma unroll
    for (int io = 0; io < 8; io++) {
        float b = bdcn[o0 + io];
        ull bb = pk2(b, b);
        acc[io * 4 + 0] = bb; acc[io * 4 + 1] = bb;
        acc[io * 4 + 2] = bb; acc[io * 4 + 3] = bb;
    }

    const float* xn = x + ((size_t)n << 20);

    for (int tap = 0; tap < 9; tap++) {
        const int ki = tap / 3, kj = tap - 3 * ki;
        const float offy = g_om[(((n * 27 + 2 * tap)     * 64 + y) << 6) + p];
        const float offx = g_om[(((n * 27 + 2 * tap + 1) * 64 + y) << 6) + p];
        const float mm   = g_om[(((n * 27 + 18 + tap)    * 64 + y) << 6) + p];
        const float mask = 1.f / (1.f + __expf(-mm));
        const float ys = (float)(y + ki - 1) + offy;
        const float xs = (float)(p + kj - 1) + offx;
        const float fy0 = floorf(ys), fx0 = floorf(xs);
        const float dy = ys - fy0, dx = xs - fx0;
        const int iy0 = (int)fy0, ix0 = (int)fx0;
        const int iy1 = iy0 + 1, ix1 = ix0 + 1;
        const bool vy0 = (iy0 >= 0) && (iy0 < 64), vy1 = (iy1 >= 0) && (iy1 < 64);
        const bool vx0 = (ix0 >= 0) && (ix0 < 64), vx1 = (ix1 >= 0) && (ix1 < 64);
        float w00 = (vy0 && vx0) ? (1.f - dy) * (1.f - dx) * mask : 0.f;
        float w01 = (vy0 && vx1) ? (1.f - dy) * dx * mask : 0.f;
        float w10 = (vy1 && vx0) ? dy * (1.f - dx) * mask : 0.f;
        float w11 = (vy1 && vx1) ? dy * dx * mask : 0.f;
        const int cy0 = min(max(iy0, 0), 63), cy1 = min(max(iy1, 0), 63);
        const int cx0 = min(max(ix0, 0), 63), cx1 = min(max(ix1, 0), 63);
        const int r0 = cy0 * 64, r1 = cy1 * 64;

        #pragma unroll 4
        for (int i = 0; i < 64; i++) {
            const int c = cg + (i << 2);
            const float* xc = xn + ((size_t)c << 12);
            float v = w00 * xc[r0 + cx0] + w01 * xc[r0 + cx1]
                    + w10 * xc[r1 + cx0] + w11 * xc[r1 + cx1];
            vsm[(c << 6) + p] = v;
        }
        __syncthreads();

        const ull* wb = (const ull*)g_wdT2 + ((size_t)tap << 16);
        #pragma unroll 2
        for (int c = 0; c < 256; c++) {
            const ulonglong2* wp = (const ulonglong2*)(wb + (c << 8) + o0);
            ulonglong2 w0 = wp[0], w1 = wp[1], w2 = wp[2], w3 = wp[3];
            const ulonglong2* vp = (const ulonglong2*)(vsm + (c << 6) + p0);
            ulonglong2 va = vp[0], vb = vp[1];
            ull wv[8] = { w0.x, w0.y, w1.x, w1.y, w2.x, w2.y, w3.x, w3.y };
            ull vv[4] = { va.x, va.y, vb.x, vb.y };
            #pragma unroll
            for (int io = 0; io < 8; io++)
                #pragma unroll
                for (int jp = 0; jp < 4; jp++)
                    ffma2(acc[io * 4 + jp], wv[io], vv[jp]);
        }
        __syncthreads();
    }

    float* ob = g_out1 + ((size_t)n << 20) + (y << 6) + p0;
    #pragma unroll
    for (int io = 0; io < 8; io++) {
        float f0,f1,f2,f3,f4,f5,f6,f7;
        upk2(acc[io * 4 + 0], f0, f1); upk2(acc[io * 4 + 1], f2, f3);
        upk2(acc[io * 4 + 2], f4, f5); upk2(acc[io * 4 + 3], f6, f7);
        float* op = ob + ((size_t)(o0 + io) << 12);
        *(float4*)op       = make_float4(f0, f1, f2, f3);
        *(float4*)(op + 4) = make_float4(f4, f5, f6, f7);
    }
}

// ---------------- per-channel reductions ------------------------------------
__global__ void k_red1() {
    int c = blockIdx.x, nb = blockIdx.y, t = threadIdx.x;
    const float4* p = (const float4*)(g_out1 + ((((size_t)nb << 8) + c) << 12));
    float s = 0.f, ss = 0.f;
    #pragma unroll
    for (int i = 0; i < 4; i++) {
        float4 v = p[t + (i << 8)];
        s  += v.x + v.y + v.z + v.w;
        ss += v.x * v.x + v.y * v.y + v.z * v.z + v.w * v.w;
    }
    for (int off = 16; off; off >>= 1) {
        s  += __shfl_down_sync(0xffffffffu, s, off);
        ss += __shfl_down_sync(0xffffffffu, ss, off);
    }
    __shared__ float as[8], bs[8];
    if ((t & 31) == 0) { as[t >> 5] = s; bs[t >> 5] = ss; }
    __syncthreads();
    if (t == 0) {
        float S = 0.f, SS = 0.f;
        for (int i = 0; i < 8; i++) { S += as[i]; SS += bs[i]; }
        atomicAdd(&g_red[c], (double)S);
        atomicAdd(&g_red[256 + c], (double)SS);
    }
}

__global__ void k_red2() {
    int c = blockIdx.x, q = blockIdx.y, t = threadIdx.x;
    const float4* p = (const float4*)(g_raw + ((((size_t)q << 8) + c) << 12));
    float s = 0.f, ss = 0.f;
    #pragma unroll
    for (int i = 0; i < 4; i++) {
        float4 v = p[t + (i << 8)];
        s  += v.x + v.y + v.z + v.w;
        ss += v.x * v.x + v.y * v.y + v.z * v.z + v.w * v.w;
    }
    for (int off = 16; off; off >>= 1) {
        s  += __shfl_down_sync(0xffffffffu, s, off);
        ss += __shfl_down_sync(0xffffffffu, ss, off);
    }
    __shared__ float as[8], bs[8];
    if ((t & 31) == 0) { as[t >> 5] = s; bs[t >> 5] = ss; }
    __syncthreads();
    if (t == 0) {
        float S = 0.f, SS = 0.f;
        for (int i = 0; i < 8; i++) { S += as[i]; SS += bs[i]; }
        atomicAdd(&g_red[512 + c], (double)S);
        atomicAdd(&g_red[768 + c], (double)SS);
    }
}

__global__ void k_stats1(const float* __restrict__ g, const float* __restrict__ b) {
    int t = threadIdx.x;
    double sum = g_red[t], sq = g_red[256 + t];
    double m = sum / 32768.0;
    float var = (float)(sq / 32768.0 - m * m);
    var = fmaxf(var, 0.f);
    float s = g[t] * rsqrtf(var + EPS);
    g_s1[t] = s;
    g_t1[t] = b[t] - (float)m * s;
}

__global__ void k_stats2(const float* __restrict__ g, const float* __restrict__ b) {
    int t = threadIdx.x;
    double sum = g_red[512 + t], sq = g_red[768 + t];
    double m = sum / 131072.0;
    float var = (float)(sq / 131072.0 - m * m);
    var = fmaxf(var, 0.f);
    float s = g[t] * rsqrtf(var + EPS);
    g_s2[t] = s;
    g_t2[t] = b[t] - (float)m * s;
}

// ---------------- conv transpose (per output parity, 4 taps) ----------------
__global__ void __launch_bounds__(256, 2) k_convt() {
    extern __shared__ float sm[];
    float* vsm = sm;                 // [256][64]
    float* ssm = sm + 16384;         // s1
    float* tsm = sm + 16640;         // t1
    const int t = threadIdx.x, ty0 = blockIdx.x, n = blockIdx.y, par = blockIdx.z;
    const int py = par >> 1, px = par & 1;
    ssm[t] = g_s1[t];
    tsm[t] = g_t1[t];
    __syncthreads();

    const int o0 = (t & 31) * 8;
    const int p0 = (t >> 5) * 8;
    const int p  = t & 63;
    const int cg = t >> 6;

    ull acc[32];
    #pragma unroll
    for (int i = 0; i < 32; i++) acc[i] = 0ull;

    const float* srcn = g_out1 + ((size_t)n << 20);

    for (int tp = 0; tp < 4; tp++) {
        const int t_y = tp >> 1, t_x = tp & 1;
        const int yy = ty0 + t_y - 1 + py;
        const int xx = p + t_x - 1 + px;
        const bool valid = (yy >= 0) && (yy < 64) && (xx >= 0) && (xx < 64);
        const float* src = srcn + yy * 64 + xx;
        #pragma unroll 4
        for (int i = 0; i < 64; i++) {
            const int c = cg + (i << 2);
            float v = 0.f;
            if (valid) {
                float r = src[(size_t)c << 12];
                v = fmaxf(ssm[c] * r + tsm[c], 0.f);
            }
            vsm[(c << 6) + p] = v;
        }
        __syncthreads();

        const ull* wb = (const ull*)g_wctT2 + (((size_t)par * 4 + tp) << 16);
        #pragma unroll 2
        for (int c = 0; c < 256; c++) {
            const ulonglong2* wp = (const ulonglong2*)(wb + (c << 8) + o0);
            ulonglong2 w0 = wp[0], w1 = wp[1], w2 = wp[2], w3 = wp[3];
            const ulonglong2* vp = (const ulonglong2*)(vsm + (c << 6) + p0);
            ulonglong2 va = vp[0], vb = vp[1];
            ull wv[8] = { w0.x, w0.y, w1.x, w1.y, w2.x, w2.y, w3.x, w3.y };
            ull vv[4] = { va.x, va.y, vb.x, vb.y };
            #pragma unroll
            for (int io = 0; io < 8; io++)
                #pragma unroll
                for (int jp = 0; jp < 4; jp++)
                    ffma2(acc[io * 4 + jp], wv[io], vv[jp]);
        }
        __syncthreads();
    }

    float* ob = g_raw + (((size_t)par * 8 + n) << 20) + (ty0 << 6) + p0;
    #pragma unroll
    for (int io = 0; io < 8; io++) {
        float f0,f1,f2,f3,f4,f5,f6,f7;
        upk2(acc[io * 4 + 0], f0, f1); upk2(acc[io * 4 + 1], f2, f3);
        upk2(acc[io * 4 + 2], f4, f5); upk2(acc[io * 4 + 3], f6, f7);
        float* op = ob + ((size_t)(o0 + io) << 12);
        *(float4*)op       = make_float4(f0, f1, f2, f3);
        *(float4*)(op + 4) = make_float4(f4, f5, f6, f7);
    }
}

// ---------------- finalize: BN2 + ReLU, de-interleave parities --------------
__global__ void k_final(float* __restrict__ out) {
    int idx = blockIdx.x * 256 + threadIdx.x;        // 16,777,216 threads
    int tx = idx & 63;
    int oy = (idx >> 6) & 127;
    int o  = (idx >> 13) & 255;
    int n  = idx >> 21;
    int py = oy & 1, ty = oy >> 1;
    size_t b0 = ((((size_t)(2 * py + 0) * 8 + n) * 256 + o) << 12) + (ty << 6) + tx;
    size_t b1 = ((((size_t)(2 * py + 1) * 8 + n) * 256 + o) << 12) + (ty << 6) + tx;
    float r0 = g_raw[b0], r1 = g_raw[b1];
    float s = g_s2[o], tt = g_t2[o];
    float2 w2;
    w2.x = fmaxf(s * r0 + tt, 0.f);
    w2.y = fmaxf(s * r1 + tt, 0.f);
    *(float2*)(out + ((((size_t)n * 256 + o) * 128 + oy) << 7) + 2 * tx) = w2;
}

// ---------------- launch ----------------------------------------------------
extern "C" void kernel_launch(void* const* d_in, const int* in_sizes, int n_in,
                              void* d_out, int out_size) {
    const float* x      = (const float*)d_in[0];
    const float* w_off  = (const float*)d_in[1];
    const float* b_off  = (const float*)d_in[2];
    const float* w_dcn  = (const float*)d_in[3];
    const float* b_dcn  = (const float*)d_in[4];
    const float* gamma1 = (const float*)d_in[5];
    const float* beta1  = (const float*)d_in[6];
    const float* w_ct   = (const float*)d_in[7];
    const float* gamma2 = (const float*)d_in[8];
    const float* beta2  = (const float*)d_in[9];
    float* out = (float*)d_out;

    cudaFuncSetAttribute(k_off,   cudaFuncAttributeMaxDynamicSharedMemorySize, 65536);
    cudaFuncSetAttribute(k_dcn,   cudaFuncAttributeMaxDynamicSharedMemorySize, 65536);
    cudaFuncSetAttribute(k_convt, cudaFuncAttributeMaxDynamicSharedMemorySize, 67584);

    prep_wd<<<(9 * 256 * 256 + 255) / 256, 256>>>(w_dcn);
    prep_wo<<<(9 * 256 * 32 + 255) / 256, 256>>>(w_off);
    prep_wct<<<(16 * 65536 + 255) / 256, 256>>>(w_ct);
    k_zero<<<1, 256>>>();

    k_off<<<dim3(64, 8), 256, 65536>>>(x, b_off);
    k_dcn<<<dim3(64, 8), 256, 65536>>>(x, b_dcn);

    k_red1<<<dim3(256, 8), 256>>>();
    k_stats1<<<1, 256>>>(gamma1, beta1);

    k_convt<<<dim3(64, 8, 4), 256, 67584>>>();

    k_red2<<<dim3(256, 32), 256>>>();
    k_stats2<<<1, 256>>>(gamma2, beta2);

    k_final<<<65536, 256>>>(out);
}